// round 1
// baseline (speedup 1.0000x reference)
#include <cuda_runtime.h>

// Problem constants
#define BATCH 32
#define TLEN  1024
#define HID   128
#define QT    128          // query tile
#define KT    128          // key tile
#define LDK   132          // padded ld for transposed K tile
#define LDSIM 132          // padded ld for sim tile

#define NTHREADS 256

// smem layout (floats):
//   q_s   : QT*HID        = 16384
//   k_t   : HID*LDK       = 16896
//   sim_s : QT*LDSIM      = 16896
//   y_s   : 128
//   lam_s : 128
//   lw_s  : 128
#define SMEM_FLOATS (QT*HID + HID*LDK + QT*LDSIM + 3*128)
#define SMEM_BYTES  (SMEM_FLOATS * 4)

__global__ __launch_bounds__(NTHREADS, 1)
void ema_kernel(const float* __restrict__ y,
                const int*   __restrict__ seq,
                const float* __restrict__ embd,
                const float* __restrict__ lam_w,
                const float* __restrict__ lam_b,
                float*       __restrict__ out)
{
    extern __shared__ float smem[];
    float* q_s   = smem;                    // [QT][HID] normalized queries
    float* k_t   = q_s + QT * HID;          // [HID][LDK] normalized keys, transposed
    float* sim_s = k_t + HID * LDK;         // [QT][LDSIM] cos-sim tile
    float* y_s   = sim_s + QT * LDSIM;      // [KT]
    float* lam_s = y_s + 128;               // [QT]
    float* lw_s  = lam_s + 128;             // [HID]

    const int tid  = threadIdx.x;
    const int lane = tid & 31;
    const int wid  = tid >> 5;

    // heavy tiles (qi large) first: blockIdx 0..31 -> qi=7, etc.
    const int batch = blockIdx.x & 31;
    const int qi    = 7 - (blockIdx.x >> 5);
    const int t0    = qi * QT;

    if (tid < HID) lw_s[tid] = lam_w[tid];
    __syncthreads();

    const float lamb = lam_b[0];

    // ---- Load Q tile: gather embd rows, normalize, compute lambda ----
    for (int r = wid; r < QT; r += 8) {
        const int t = t0 + r;
        const int e = seq[batch * TLEN + t];
        const float* wrow = embd + (size_t)e * HID;
        float v0 = wrow[lane];
        float v1 = wrow[lane + 32];
        float v2 = wrow[lane + 64];
        float v3 = wrow[lane + 96];
        float ss = v0*v0 + v1*v1 + v2*v2 + v3*v3;
        float dl = v0*lw_s[lane] + v1*lw_s[lane+32] + v2*lw_s[lane+64] + v3*lw_s[lane+96];
        #pragma unroll
        for (int off = 16; off; off >>= 1) {
            ss += __shfl_xor_sync(0xffffffffu, ss, off);
            dl += __shfl_xor_sync(0xffffffffu, dl, off);
        }
        const float inv = rsqrtf(ss);
        q_s[r*HID + lane]      = v0 * inv;
        q_s[r*HID + lane + 32] = v1 * inv;
        q_s[r*HID + lane + 64] = v2 * inv;
        q_s[r*HID + lane + 96] = v3 * inv;
        if (lane == 0) lam_s[r] = __expf(dl + lamb);
    }
    __syncthreads();

    // Per-row running state (thread tid < 128 owns query row tid)
    float Dr = 0.f, Sr = 0.f, Yr = 0.f, lam_r = 0.f;
    if (tid < QT) lam_r = lam_s[tid];

    const int txl = tid & 15;
    const int tyl = tid >> 4;
    const int r0 = tyl * 8, c0 = txl * 8;

    // ---- Loop key blocks in DESCENDING s (suffix accumulation) ----
    for (int kb = qi; kb >= 0; --kb) {
        __syncthreads();   // previous scan phase done reading y_s/sim_s

        // Load K block transposed: k_t[h][c], normalized; y into y_s
        for (int c = wid; c < KT; c += 8) {
            const int s = kb * KT + c;
            const int e = seq[batch * TLEN + s];
            const float* wrow = embd + (size_t)e * HID;
            float v0 = wrow[lane];
            float v1 = wrow[lane + 32];
            float v2 = wrow[lane + 64];
            float v3 = wrow[lane + 96];
            float ss = v0*v0 + v1*v1 + v2*v2 + v3*v3;
            #pragma unroll
            for (int off = 16; off; off >>= 1)
                ss += __shfl_xor_sync(0xffffffffu, ss, off);
            const float inv = rsqrtf(ss);
            k_t[(lane)      * LDK + c] = v0 * inv;
            k_t[(lane + 32) * LDK + c] = v1 * inv;
            k_t[(lane + 64) * LDK + c] = v2 * inv;
            k_t[(lane + 96) * LDK + c] = v3 * inv;
            if (lane == 0) y_s[c] = y[batch * TLEN + s];
        }
        __syncthreads();

        // ---- 128x128x128 fp32 GEMM, 8x8 register tile per thread ----
        float acc[8][8];
        #pragma unroll
        for (int i = 0; i < 8; i++)
            #pragma unroll
            for (int j = 0; j < 8; j++) acc[i][j] = 0.f;

        #pragma unroll 1
        for (int h = 0; h < HID; h += 4) {
            float aa[8][4], bb[4][8];
            #pragma unroll
            for (int i = 0; i < 8; i++) {
                float4 t4 = *(const float4*)&q_s[(r0 + i) * HID + h];
                aa[i][0] = t4.x; aa[i][1] = t4.y; aa[i][2] = t4.z; aa[i][3] = t4.w;
            }
            #pragma unroll
            for (int hh = 0; hh < 4; hh++) {
                float4 u  = *(const float4*)&k_t[(h + hh) * LDK + c0];
                float4 w4 = *(const float4*)&k_t[(h + hh) * LDK + c0 + 4];
                bb[hh][0] = u.x;  bb[hh][1] = u.y;  bb[hh][2] = u.z;  bb[hh][3] = u.w;
                bb[hh][4] = w4.x; bb[hh][5] = w4.y; bb[hh][6] = w4.z; bb[hh][7] = w4.w;
            }
            #pragma unroll
            for (int hh = 0; hh < 4; hh++)
                #pragma unroll
                for (int i = 0; i < 8; i++)
                    #pragma unroll
                    for (int j = 0; j < 8; j++)
                        acc[i][j] = fmaf(aa[i][hh], bb[hh][j], acc[i][j]);
        }

        // store sim tile
        #pragma unroll
        for (int i = 0; i < 8; i++) {
            *(float4*)&sim_s[(r0 + i) * LDSIM + c0]     =
                make_float4(acc[i][0], acc[i][1], acc[i][2], acc[i][3]);
            *(float4*)&sim_s[(r0 + i) * LDSIM + c0 + 4] =
                make_float4(acc[i][4], acc[i][5], acc[i][6], acc[i][7]);
        }
        __syncthreads();

        // ---- Scan phase: thread tid owns query row tid ----
        if (tid < QT) {
            const float* row = &sim_s[tid * LDSIM];
            // strictly-causal mask: s < t.  For kb < qi all s qualify;
            // diagonal block: local col c qualifies iff c < tid.
            const int cmax = (kb == qi) ? (tid - 1) : (KT - 1);
            for (int c = cmax; c >= 0; --c) {
                float v = (row[c] + 1.0f) * 0.5f;   // (cos+1)/2
                Dr += v;                            // inclusive suffix sum
                float w = v * __expf(-lam_r * Dr);
                Sr += w;
                Yr = fmaf(y_s[c], w, Yr);
            }
        }
    }

    if (tid < QT) {
        float o = Yr / (Sr + 1e-6f);
        o = fminf(fmaxf(o, 0.01f), 0.99f);
        out[batch * TLEN + t0 + tid] = o;
    }
}

extern "C" void kernel_launch(void* const* d_in, const int* in_sizes, int n_in,
                              void* d_out, int out_size)
{
    const float* y    = (const float*)d_in[0];
    const int*   seq  = (const int*)  d_in[1];
    const float* embd = (const float*)d_in[2];
    const float* lw   = (const float*)d_in[3];
    const float* lb   = (const float*)d_in[4];
    float* out = (float*)d_out;

    cudaFuncSetAttribute(ema_kernel,
                         cudaFuncAttributeMaxDynamicSharedMemorySize,
                         SMEM_BYTES);

    ema_kernel<<<BATCH * (TLEN / QT), NTHREADS, SMEM_BYTES>>>(
        y, seq, embd, lw, lb, out);
}